// round 16
// baseline (speedup 1.0000x reference)
#include <cuda_runtime.h>
#include <cuda_fp16.h>
#include <math.h>
#include <stdint.h>

#define NB   16
#define CC   256
#define CIN  192
#define CE   768
#define SS   1024
#define NHEAD 4

#define EPSV 1e-4f
#define SILU_SCALE 1.6778523489932886f   // 1/0.596
#define CA 0.9191450300180579f           // 0.7/sqrt(0.58)
#define CB 0.3939192985791677f           // 0.3/sqrt(0.58)

typedef __half fp16;

// ---------------- static device scratch ----------------
__device__ fp16 g_a16[NB * SS * CC];
__device__ fp16 g_b16[NB * SS * CC];
__device__ fp16 g_w_skip[CC * CIN];
__device__ fp16 g_w_res0[CC * CC * 9];
__device__ fp16 g_w_res1[CC * CC * 9];
__device__ fp16 g_w_qkv[3 * CC * CC];       // rows permuted (h, which, cph)
__device__ fp16 g_w_proj[CC * CC];
__device__ float g_c[NB * CC];
__device__ float g_x[NB * SS * CC];
__device__ fp16 g_q16[64 * SS * 64];
__device__ fp16 g_k16[64 * SS * 64];
__device__ fp16 g_v16[64 * SS * 64];

__device__ __forceinline__ float mp_silu(float v) {
    return v / (1.f + __expf(-v)) * SILU_SCALE;
}
__device__ __forceinline__ uint32_t packf(float a, float b) {
    __half2 h = __floats2half2_rn(a, b);
    return *(uint32_t*)&h;
}
__device__ __forceinline__ uint32_t smem_u32(const void* p) {
    uint32_t a;
    asm("{ .reg .u64 t; cvta.to.shared.u64 t, %1; cvt.u32.u64 %0, t; }" : "=r"(a) : "l"(p));
    return a;
}
__device__ __forceinline__ void cpa16(uint32_t d, const void* s, int sz) {
    asm volatile("cp.async.cg.shared.global [%0], [%1], 16, %2;"
                 :: "r"(d), "l"(s), "r"(sz));
}
__device__ __forceinline__ void ldsm4(uint32_t* r, uint32_t addr) {
    asm volatile("ldmatrix.sync.aligned.m8n8.x4.shared.b16 {%0,%1,%2,%3}, [%4];"
                 : "=r"(r[0]), "=r"(r[1]), "=r"(r[2]), "=r"(r[3]) : "r"(addr));
}
__device__ __forceinline__ void ldsm4t(uint32_t* r, uint32_t addr) {
    asm volatile("ldmatrix.sync.aligned.m8n8.x4.trans.shared.b16 {%0,%1,%2,%3}, [%4];"
                 : "=r"(r[0]), "=r"(r[1]), "=r"(r[2]), "=r"(r[3]) : "r"(addr));
}
__device__ __forceinline__ void mma16816(float* c, const uint32_t* a, const uint32_t* b) {
    asm volatile(
        "mma.sync.aligned.m16n8k16.row.col.f32.f16.f16.f32 "
        "{%0,%1,%2,%3}, {%4,%5,%6,%7}, {%8,%9}, {%0,%1,%2,%3};"
        : "+f"(c[0]), "+f"(c[1]), "+f"(c[2]), "+f"(c[3])
        : "r"(a[0]), "r"(a[1]), "r"(a[2]), "r"(a[3]), "r"(b[0]), "r"(b[1]));
}
__device__ __forceinline__ uint32_t swz(uint32_t byteoff, uint32_t row) {
    return byteoff ^ ((row & 7u) * 16u);
}
__device__ __forceinline__ uint32_t ex2h2(uint32_t t) {
    uint32_t r;
    asm volatile("ex2.approx.f16x2 %0, %1;" : "=r"(r) : "r"(t));
    return r;
}

// ---------------- unified prep: weights + emb modulation + input split -----
__global__ void k_prep_all(const float* __restrict__ w_skip,
                           const float* __restrict__ w_res0,
                           const float* __restrict__ w_res1,
                           const float* __restrict__ w_qkv,
                           const float* __restrict__ w_proj,
                           const float* __restrict__ w_emb,
                           const float* __restrict__ emb_g,
                           const float* __restrict__ emb,
                           const float* __restrict__ xin) {
    int b = blockIdx.x;
    if (b >= 2048) {
        __shared__ float t[32][33];
        int blk = b - 2048;
        int sblk = blk & 31, rest = blk >> 5;
        int cblk = rest % 6, n = rest / 6;
        int s0 = sblk * 32, c0 = cblk * 32;
        int li = threadIdx.x & 31, gi = threadIdx.x >> 5;
#pragma unroll
        for (int it = 0; it < 4; it++) {
            int c = gi + it * 8;
            t[c][li] = xin[((long)n * CIN + c0 + c) * SS + s0 + li];
        }
        __syncthreads();
#pragma unroll
        for (int it = 0; it < 4; it++) {
            int s = gi + it * 8;
            g_a16[((long)n * SS + s0 + s) * CIN + c0 + li] = __float2half(t[li][s]);
        }
        return;
    }
    const float* src;
    fp16* dst = nullptr;
    int cin, taps = 1, o, perm = 0;
    float gain = 1.f;
    bool isf32 = false;
    if (b < 256)       { src = w_skip; dst = g_w_skip; cin = CIN; o = b; }
    else if (b < 512)  { src = w_res0; dst = g_w_res0; cin = CC; taps = 9; o = b - 256; }
    else if (b < 768)  { src = w_res1; dst = g_w_res1; cin = CC; taps = 9; o = b - 512; }
    else if (b < 1536) { src = w_qkv;  dst = g_w_qkv;  cin = CC; o = b - 768; perm = 1; }
    else if (b < 1792) { src = w_proj; dst = g_w_proj; cin = CC; o = b - 1536; }
    else               { src = w_emb;  cin = CE; o = b - 1792; gain = *emb_g; isf32 = true; }

    int fan = cin * taps;
    const float* row = src + (long)o * fan;
    float s = 0.f;
    for (int i = threadIdx.x; i < fan; i += 256) { float v = row[i]; s += v * v; }
    __shared__ float red[256];
    red[threadIdx.x] = s;
    __syncthreads();
    for (int off = 128; off > 0; off >>= 1) {
        if (threadIdx.x < off) red[threadIdx.x] += red[threadIdx.x + off];
        __syncthreads();
    }
    float sf = sqrtf((float)fan);
    float scale = gain / (sf * (EPSV + sqrtf(red[0]) / sf));
    if (isf32) {
        __shared__ float srow[CE];
        for (int i = threadIdx.x; i < CE; i += 256) srow[i] = row[i] * scale;
        __syncthreads();
        int wid = threadIdx.x >> 5, lane = threadIdx.x & 31;
#pragma unroll
        for (int rep = 0; rep < 2; rep++) {
            int n = wid * 2 + rep;
            const float* e = emb + n * CE;
            float sum = 0.f;
            for (int k = lane; k < CE; k += 32) sum += e[k] * srow[k];
#pragma unroll
            for (int o2 = 16; o2 > 0; o2 >>= 1)
                sum += __shfl_xor_sync(0xffffffffu, sum, o2);
            if (lane == 0) g_c[n * CC + o] = sum + 1.0f;
        }
        return;
    }
    int od = o;
    if (perm) {
        int h = o / 192, r = o - h * 192;
        od = h * 192 + (r % 3) * 64 + r / 3;
    }
    fp16* drow = dst + (long)od * fan;
    if (taps == 1) {
        for (int i = threadIdx.x; i < fan; i += 256)
            drow[i] = __float2half(row[i] * scale);
    } else {
        for (int i = threadIdx.x; i < fan; i += 256) {
            int tap = i >> 8, ci = i & 255;
            drow[i] = __float2half(row[ci * 9 + tap] * scale);
        }
    }
}

// ---------------- fused skip conv (192->256) + pixel norm + silu -----------
#define SSTAGE 49152
#define SSMEM  (3 * SSTAGE)
__global__ __launch_bounds__(512, 1) void k_skipnorm(const fp16* __restrict__ inA,
                                                     const fp16* __restrict__ wA) {
    extern __shared__ char smem[];
    const int tid = threadIdx.x, lane = tid & 31, wid = tid >> 5;
    const int n = blockIdx.y, pxb = blockIdx.x * 128;
    const int wco = wid >> 2, wpx = wid & 3;
    const uint32_t sbase = smem_u32(smem);

    float acc[64];
#pragma unroll
    for (int i = 0; i < 64; i++) acc[i] = 0.f;

    auto load_chunk = [&](int c, int stage) {
        int ci0 = c << 6;
        uint32_t b = sbase + stage * SSTAGE;
#pragma unroll
        for (int rep = 0; rep < 4; rep++) {
            int idx = tid + rep * 512;
            int r = idx >> 3, seg = idx & 7;
            long aoff = (long)r * CIN + ci0 + seg * 8;
            cpa16(b + r * 128 + swz(seg * 16, r), wA + aoff, 16);
        }
#pragma unroll
        for (int rep = 0; rep < 2; rep++) {
            int idx = tid + rep * 512;
            int p = idx >> 3, seg = idx & 7;
            long soff = ((long)n * SS + pxb + p) * CIN + ci0 + seg * 8;
            cpa16(b + 32768 + p * 128 + swz(seg * 16, p), inA + soff, 16);
        }
        asm volatile("cp.async.commit_group;" ::: "memory");
    };

    load_chunk(0, 0);
    load_chunk(1, 1);
    load_chunk(2, 2);
    for (int c = 0; c < 3; c++) {
        if (c + 1 < 3) {
            asm volatile("cp.async.wait_group 1;" ::: "memory");
        } else {
            asm volatile("cp.async.wait_group 0;" ::: "memory");
        }
        __syncthreads();
        uint32_t b = sbase + c * SSTAGE;
#pragma unroll
        for (int k16 = 0; k16 < 4; k16++) {
            uint32_t Bh[8];
#pragma unroll
            for (int t = 0; t < 2; t++) {
                int sub = lane >> 3, r7 = lane & 7;
                uint32_t prow = wpx * 32 + (2 * t + (sub >> 1)) * 8 + r7;
                ldsm4(&Bh[4 * t],
                      b + 32768 + prow * 128 + swz(k16 * 32 + (sub & 1) * 16, prow));
            }
#pragma unroll
            for (int mt = 0; mt < 4; mt++) {
                uint32_t Ah[4];
                uint32_t mrow = wco * 64 + mt * 16 + (lane & 15);
                ldsm4(Ah, b + mrow * 128 + swz(k16 * 32 + (lane >> 4) * 16, mrow));
#pragma unroll
                for (int nt = 0; nt < 4; nt++)
                    mma16816(acc + mt * 16 + nt * 4, Ah, &Bh[2 * nt]);
            }
        }
        __syncthreads();
    }

    float* sT = (float*)smem;
#pragma unroll
    for (int mt = 0; mt < 4; mt++)
#pragma unroll
        for (int nt = 0; nt < 4; nt++)
#pragma unroll
            for (int r = 0; r < 4; r++) {
                int row = wco * 64 + mt * 16 + (lane >> 2) + ((r >> 1) << 3);
                int col = wpx * 32 + nt * 8 + ((lane & 3) << 1) + (r & 1);
                sT[col * 260 + row] = acc[mt * 16 + nt * 4 + r];
            }
    __syncthreads();

    int px = tid >> 2, q = tid & 3;
    float* sRow = sT + px * 260 + q * 64;
    float sum = 0.f;
#pragma unroll
    for (int j = 0; j < 64; j++) sum += sRow[j] * sRow[j];
    sum += __shfl_xor_sync(0xffffffffu, sum, 1);
    sum += __shfl_xor_sync(0xffffffffu, sum, 2);
    float scale = 1.f / (EPSV + sqrtf(sum) * 0.0625f);
    long ob = ((long)n * SS + pxb + px) * CC + q * 64;
#pragma unroll
    for (int j = 0; j < 64; j += 4) {
        float4 v = *(const float4*)&sRow[j];
        v.x *= scale; v.y *= scale; v.z *= scale; v.w *= scale;
        *(float4*)&g_x[ob + j] = v;
        *(uint2*)(g_a16 + ob + j) =
            make_uint2(packf(mp_silu(v.x), mp_silu(v.y)),
                       packf(mp_silu(v.z), mp_silu(v.w)));
    }
}

// ---------------- fp16 mma.sync GEMM / implicit conv: 128x128, K=64 --------
// A-fragment software pipeline: prefetch next (k16,mt) before current MMAs.
#define GSTAGE 32768
#define GSMEM  (3 * GSTAGE)
__global__ __launch_bounds__(256, 2) void k_gemm(
    const fp16* __restrict__ inA, const fp16* __restrict__ wA,
    float* __restrict__ outF, fp16* __restrict__ out16,
    const float* __restrict__ res, const float* __restrict__ cvec,
    int cin, int cout, int taps, int mode) {
    extern __shared__ char smem[];
    const int tid = threadIdx.x, lane = tid & 31, wid = tid >> 5;
    const int n = blockIdx.z, co0 = blockIdx.y * 128, pxb = blockIdx.x * 128;
    const int wco = wid >> 2, wpx = wid & 3;
    const int cpt = cin >> 6;
    const int nch = taps * cpt;
    const long Ktot = (long)taps * cin;
    const uint32_t sbase = smem_u32(smem);

    float acc[64];
#pragma unroll
    for (int i = 0; i < 64; i++) acc[i] = 0.f;

    auto load_chunk = [&](int c, int stage) {
        int tap = c / cpt;
        int ci0 = (c - tap * cpt) << 6;
        int dy = (taps == 9) ? tap / 3 - 1 : 0;
        int dx = (taps == 9) ? tap % 3 - 1 : 0;
        uint32_t b = sbase + stage * GSTAGE;
#pragma unroll
        for (int rep = 0; rep < 4; rep++) {
            int idx = tid + rep * 256;
            int r = idx >> 3, seg = idx & 7;
            long aoff = (long)(co0 + r) * Ktot + (long)c * 64 + seg * 8;
            cpa16(b + r * 128 + swz(seg * 16, r), wA + aoff, 16);
        }
#pragma unroll
        for (int rep = 0; rep < 4; rep++) {
            int idx = tid + rep * 256;
            int p = idx >> 3, seg = idx & 7;
            int s = pxb + p;
            int hh = (s >> 5) + dy, ww = (s & 31) + dx;
            int valid = ((unsigned)hh < 32u) && ((unsigned)ww < 32u);
            long soff = ((long)n * SS + (valid ? hh * 32 + ww : 0)) * cin + ci0 + seg * 8;
            cpa16(b + 16384 + p * 128 + swz(seg * 16, p), inA + soff, valid ? 16 : 0);
        }
        asm volatile("cp.async.commit_group;" ::: "memory");
    };

    // per-lane A fragment address helper
    const uint32_t arow_lo = (lane & 15);
    const uint32_t ak_half = (lane >> 4) * 16;
    auto ldA = [&](uint32_t b, int k16, int mt, uint32_t* dstreg) {
        uint32_t mrow = wco * 64 + mt * 16 + arow_lo;
        ldsm4(dstreg, b + mrow * 128 + swz(k16 * 32 + ak_half, mrow));
    };

    load_chunk(0, 0);
    if (nch > 1) load_chunk(1, 1);
    int stage = 0;
    for (int c = 0; c < nch; c++) {
        if (c + 1 < nch) {
            asm volatile("cp.async.wait_group 1;" ::: "memory");
        } else {
            asm volatile("cp.async.wait_group 0;" ::: "memory");
        }
        __syncthreads();
        if (c + 2 < nch) {
            int ps = stage + 2;
            if (ps >= 3) ps -= 3;
            load_chunk(c + 2, ps);
        }
        uint32_t b = sbase + stage * GSTAGE;

        // software-pipelined fragment loop: Afrag double buffer
        uint32_t Afrag[2][4];
        ldA(b, 0, 0, Afrag[0]);
#pragma unroll
        for (int k16 = 0; k16 < 4; k16++) {
            uint32_t Bh[8];
#pragma unroll
            for (int t = 0; t < 2; t++) {
                int sub = lane >> 3, r7 = lane & 7;
                uint32_t prow = wpx * 32 + (2 * t + (sub >> 1)) * 8 + r7;
                ldsm4(&Bh[4 * t],
                      b + 16384 + prow * 128 + swz(k16 * 32 + (sub & 1) * 16, prow));
            }
#pragma unroll
            for (int mt = 0; mt < 4; mt++) {
                const int cur = (k16 * 4 + mt) & 1;
                int nm = mt + 1, nk = k16;
                if (nm == 4) { nm = 0; nk++; }
                if (nk < 4) ldA(b, nk, nm, Afrag[cur ^ 1]);
#pragma unroll
                for (int nt = 0; nt < 4; nt++)
                    mma16816(acc + mt * 16 + nt * 4, Afrag[cur], &Bh[2 * nt]);
            }
        }
        stage++;
        if (stage >= 3) stage = 0;
    }
    __syncthreads();

    // ---- single-round epilogue ----
    float* sT = (float*)smem;
#pragma unroll
    for (int mt = 0; mt < 4; mt++)
#pragma unroll
        for (int nt = 0; nt < 4; nt++)
#pragma unroll
            for (int r = 0; r < 4; r++) {
                int row = wco * 64 + mt * 16 + (lane >> 2) + ((r >> 1) << 3);
                int col = wpx * 32 + nt * 8 + ((lane & 3) << 1) + (r & 1);
                sT[col * 132 + row] = acc[mt * 16 + nt * 4 + r];
            }
    __syncthreads();

    int px = tid >> 1, half = tid & 1;
    long srow = (long)n * SS + pxb + px;
    float* sRow = sT + px * 132 + half * 64;
    int cg0 = co0 + half * 64;
    if (mode == 1) {
        long ob = srow * CC + cg0;
#pragma unroll
        for (int j = 0; j < 64; j += 4) {
            float4 v = *(const float4*)&sRow[j];
            float4 cv = *(const float4*)&cvec[n * CC + cg0 + j];
            *(uint2*)(out16 + ob + j) =
                make_uint2(packf(mp_silu(v.x * cv.x), mp_silu(v.y * cv.y)),
                           packf(mp_silu(v.z * cv.z), mp_silu(v.w * cv.w)));
        }
    } else if (mode == 2) {
        long ob = srow * CC + cg0;
#pragma unroll
        for (int j = 0; j < 64; j += 4) {
            float4 v = *(const float4*)&sRow[j];
            float4 r4 = *(const float4*)&res[ob + j];
            v.x = CA * r4.x + CB * v.x; v.y = CA * r4.y + CB * v.y;
            v.z = CA * r4.z + CB * v.z; v.w = CA * r4.w + CB * v.w;
            *(float4*)&outF[ob + j] = v;
            *(uint2*)(out16 + ob + j) = make_uint2(packf(v.x, v.y), packf(v.z, v.w));
        }
    } else if (mode == 3) {
        float sum = 0.f;
#pragma unroll
        for (int j = 0; j < 64; j++) sum += sRow[j] * sRow[j];
        float scale = 1.f / (EPSV + sqrtf(sum) * 0.125f);
        int g64 = (cg0 >> 6);
        int h = g64 / 3, which = g64 - h * 3;
        fp16* dst = (which == 0) ? g_q16 : (which == 1) ? g_k16 : g_v16;
        long ob = ((long)(n * NHEAD + h) * SS + pxb + px) * 64;
#pragma unroll
        for (int j = 0; j < 64; j += 2)
            *(uint32_t*)(dst + ob + j) = packf(sRow[j] * scale, sRow[j + 1] * scale);
    } else {
        long ob = srow * CC + cg0;
#pragma unroll
        for (int j = 0; j < 64; j += 4) {
            float4 v = *(const float4*)&sRow[j];
            float4 r4 = *(const float4*)&res[ob + j];
            v.x = fminf(fmaxf(CA * r4.x + CB * v.x, -256.f), 256.f);
            v.y = fminf(fmaxf(CA * r4.y + CB * v.y, -256.f), 256.f);
            v.z = fminf(fmaxf(CA * r4.z + CB * v.z, -256.f), 256.f);
            v.w = fminf(fmaxf(CA * r4.w + CB * v.w, -256.f), 256.f);
            *(float4*)&sRow[j] = v;
        }
        __syncthreads();
        int co = tid >> 1, hp = tid & 1;
        float* op = outF + ((long)n * CC + co0 + co) * SS + pxb + hp * 64;
#pragma unroll
        for (int j = 0; j < 64; j += 4) {
            float4 v;
            v.x = sT[(hp * 64 + j + 0) * 132 + co];
            v.y = sT[(hp * 64 + j + 1) * 132 + co];
            v.z = sT[(hp * 64 + j + 2) * 132 + co];
            v.w = sT[(hp * 64 + j + 3) * 132 + co];
            *(float4*)&op[j] = v;
        }
    }
}

// ---------------- fp16 MMA flash attention: 128-key tiles ----------------
#define ASTAGE 36864
#define ATT_SMEM (3 * ASTAGE)
__global__ __launch_bounds__(256, 2) void k_fattn() {
    extern __shared__ char smem[];
    const int tid = threadIdx.x, lane = tid & 31, wid = tid >> 5;
    const int nh = blockIdx.y, qb = blockIdx.x * 128;
    const int n = nh >> 2, h = nh & 3;
    const uint32_t sb = smem_u32(smem);
    const long nhb = (long)nh * SS * 64;
    const fp16* kp = g_k16 + nhb;
    const fp16* vp = g_v16 + nhb;
    const float C1 = 0.125f * 1.4426950408889634f;
    const float C2 = 8.0f * 1.4426950408889634f;

    {
        const fp16* qp = g_q16 + nhb + (long)qb * 64;
        for (int i = tid; i < 1024; i += 256) {
            int r = i >> 3, seg = i & 7;
            cpa16(sb + r * 144 + seg * 16, qp + r * 64 + seg * 8, 16);
        }
        asm volatile("cp.async.commit_group;" ::: "memory");
        asm volatile("cp.async.wait_group 0;" ::: "memory");
        __syncthreads();
    }
    uint32_t qf[4][4];
    {
        int r = wid * 16 + (lane & 15);
        int halfk = lane >> 4;
#pragma unroll
        for (int kc = 0; kc < 4; kc++)
            ldsm4(qf[kc], sb + r * 144 + (kc * 16 + halfk * 8) * 2);
    }
    __syncthreads();

    auto load_kv = [&](int t, int stg) {
        uint32_t b = sb + stg * ASTAGE;
#pragma unroll
        for (int rep = 0; rep < 4; rep++) {
            int i = tid + rep * 256;
            int r = i >> 3, seg = i & 7;
            long off = ((long)t * 128 + r) * 64 + seg * 8;
            uint32_t d = b + r * 144 + seg * 16;
            cpa16(d, kp + off, 16);
            cpa16(d + 18432, vp + off, 16);
        }
        asm volatile("cp.async.commit_group;" ::: "memory");
    };

    float l0 = 0.f, l1 = 0.f;
    float acc[8][4];
#pragma unroll
    for (int j = 0; j < 8; j++)
#pragma unroll
        for (int i = 0; i < 4; i++) acc[j][i] = 0.f;

    load_kv(0, 0);
    load_kv(1, 1);
    int stg = 0;
    for (int t = 0; t < 8; t++) {
        if (t + 1 < 8) {
            asm volatile("cp.async.wait_group 1;" ::: "memory");
        } else {
            asm volatile("cp.async.wait_group 0;" ::: "memory");
        }
        __syncthreads();
        if (t + 2 < 8) {
            int ps = stg + 2;
            if (ps >= 3) ps -= 3;
            load_kv(t + 2, ps);
        }
        uint32_t kb = sb + stg * ASTAGE;
        const int g = lane >> 3, r7 = lane & 7;

        uint32_t pc01[16], pc23[16];
#pragma unroll
        for (int ntp = 0; ntp < 8; ntp++) {
            float s0[4] = {0.f, 0.f, 0.f, 0.f};
            float s1[4] = {0.f, 0.f, 0.f, 0.f};
#pragma unroll
            for (int kc = 0; kc < 4; kc++) {
                uint32_t bh[4];
                ldsm4(bh, kb + (ntp * 16 + (g >> 1) * 8 + r7) * 144
                          + (kc * 16 + (g & 1) * 8) * 2);
                mma16816(s0, qf[kc], bh);
                mma16816(s1, qf[kc], bh + 2);
            }
            uint32_t a0 = ex2h2(packf(s0[0] * C1 - C2, s0[1] * C1 - C2));
            uint32_t b0 = ex2h2(packf(s0[2] * C1 - C2, s0[3] * C1 - C2));
            uint32_t a1 = ex2h2(packf(s1[0] * C1 - C2, s1[1] * C1 - C2));
            uint32_t b1 = ex2h2(packf(s1[2] * C1 - C2, s1[3] * C1 - C2));
            pc01[2 * ntp] = a0; pc23[2 * ntp] = b0;
            pc01[2 * ntp + 1] = a1; pc23[2 * ntp + 1] = b1;
            float2 fa0 = __half22float2(*(__half2*)&a0);
            float2 fb0 = __half22float2(*(__half2*)&b0);
            float2 fa1 = __half22float2(*(__half2*)&a1);
            float2 fb1 = __half22float2(*(__half2*)&b1);
            l0 += fa0.x + fa0.y + fa1.x + fa1.y;
            l1 += fb0.x + fb0.y + fb1.x + fb1.y;
        }
#pragma unroll
        for (int kk = 0; kk < 8; kk++) {
            uint32_t ph[4];
            ph[0] = pc01[2 * kk];
            ph[1] = pc23[2 * kk];
            ph[2] = pc01[2 * kk + 1];
            ph[3] = pc23[2 * kk + 1];
#pragma unroll
            for (int ctp = 0; ctp < 4; ctp++) {
                uint32_t vh4[4];
                ldsm4t(vh4, kb + 18432 + (kk * 16 + (g & 1) * 8 + r7) * 144
                            + (ctp * 16 + (g >> 1) * 8) * 2);
                mma16816(acc[2 * ctp], ph, vh4);
                mma16816(acc[2 * ctp + 1], ph, vh4 + 2);
            }
        }
        stg++;
        if (stg >= 3) stg = 0;
    }

    l0 += __shfl_xor_sync(0xffffffffu, l0, 1);
    l0 += __shfl_xor_sync(0xffffffffu, l0, 2);
    l1 += __shfl_xor_sync(0xffffffffu, l1, 1);
    l1 += __shfl_xor_sync(0xffffffffu, l1, 2);
    float i0 = 1.f / l0, i1 = 1.f / l1;
    int t4 = lane & 3;
    int s0r = qb + wid * 16 + (lane >> 2);
    long b0 = ((long)n * SS + s0r) * CC + h * 64;
    long b1 = ((long)n * SS + s0r + 8) * CC + h * 64;
#pragma unroll
    for (int j = 0; j < 8; j++) {
        int ch = j * 8 + t4 * 2;
        *(uint32_t*)(g_b16 + b0 + ch) = packf(acc[j][0] * i0, acc[j][1] * i0);
        *(uint32_t*)(g_b16 + b1 + ch) = packf(acc[j][2] * i1, acc[j][3] * i1);
    }
}

// ---------------- launcher ----------------
extern "C" void kernel_launch(void* const* d_in, const int* in_sizes, int n_in,
                              void* d_out, int out_size) {
    const float* x      = (const float*)d_in[0];
    const float* emb    = (const float*)d_in[1];
    const float* w_skip = (const float*)d_in[2];
    const float* w_res0 = (const float*)d_in[3];
    const float* w_res1 = (const float*)d_in[4];
    const float* w_emb  = (const float*)d_in[5];
    const float* emb_g  = (const float*)d_in[6];
    const float* w_qkv  = (const float*)d_in[7];
    const float* w_proj = (const float*)d_in[8];
    float* out = (float*)d_out;

    fp16 *p_a16, *p_b16, *pw_skip, *pw_res0, *pw_res1, *pw_qkv, *pw_proj;
    float *p_x, *p_c;
    cudaGetSymbolAddress((void**)&p_a16, g_a16);
    cudaGetSymbolAddress((void**)&p_b16, g_b16);
    cudaGetSymbolAddress((void**)&pw_skip, g_w_skip);
    cudaGetSymbolAddress((void**)&pw_res0, g_w_res0);
    cudaGetSymbolAddress((void**)&pw_res1, g_w_res1);
    cudaGetSymbolAddress((void**)&pw_qkv, g_w_qkv);
    cudaGetSymbolAddress((void**)&pw_proj, g_w_proj);
    cudaGetSymbolAddress((void**)&p_x, g_x);
    cudaGetSymbolAddress((void**)&p_c, g_c);

    cudaFuncSetAttribute(k_gemm, cudaFuncAttributeMaxDynamicSharedMemorySize, GSMEM);
    cudaFuncSetAttribute(k_fattn, cudaFuncAttributeMaxDynamicSharedMemorySize, ATT_SMEM);
    cudaFuncSetAttribute(k_skipnorm, cudaFuncAttributeMaxDynamicSharedMemorySize, SSMEM);

    k_prep_all<<<2048 + 3072, 256>>>(w_skip, w_res0, w_res1, w_qkv, w_proj,
                                     w_emb, emb_g, emb, x);
    k_skipnorm<<<dim3(8, NB), 512, SSMEM>>>(p_a16, pw_skip);
    // res0: silu(conv3x3 * c) -> b16
    k_gemm<<<dim3(8, 2, NB), 256, GSMEM>>>(p_a16, pw_res0, nullptr, p_b16,
                                           nullptr, p_c, CC, CC, 9, 1);
    // res1: x = CA*x + CB*conv3x3 -> fp32 x + a16
    k_gemm<<<dim3(8, 2, NB), 256, GSMEM>>>(p_b16, pw_res1, p_x, p_a16,
                                           p_x, nullptr, CC, CC, 9, 2);
    // qkv conv (256->768) + fused head-channel norm -> q/k/v fp16
    k_gemm<<<dim3(8, 6, NB), 256, GSMEM>>>(p_a16, pw_qkv, nullptr, nullptr,
                                           nullptr, nullptr, CC, 3 * CC, 1, 3);
    // fp16 MMA flash attention (128-key tiles) -> b16
    k_fattn<<<dim3(SS / 128, NB * NHEAD), 256, ATT_SMEM>>>();
    // proj + mp_sum + clip -> d_out (NCHW)
    k_gemm<<<dim3(8, 2, NB), 256, GSMEM>>>(p_b16, pw_proj, out, nullptr,
                                           p_x, nullptr, CC, CC, 1, 4);
}

// round 17
// speedup vs baseline: 1.0514x; 1.0514x over previous
#include <cuda_runtime.h>
#include <cuda_fp16.h>
#include <math.h>
#include <stdint.h>

#define NB   16
#define CC   256
#define CIN  192
#define CE   768
#define SS   1024
#define NHEAD 4

#define EPSV 1e-4f
#define SILU_SCALE 1.6778523489932886f   // 1/0.596
#define CA 0.9191450300180579f           // 0.7/sqrt(0.58)
#define CB 0.3939192985791677f           // 0.3/sqrt(0.58)

typedef __half fp16;

// ---------------- static device scratch ----------------
__device__ fp16 g_a16[NB * SS * CC];
__device__ fp16 g_b16[NB * SS * CC];
__device__ fp16 g_w_skip[CC * CIN];
__device__ fp16 g_w_res0[CC * CC * 9];
__device__ fp16 g_w_res1[CC * CC * 9];
__device__ fp16 g_w_qkv[3 * CC * CC];       // rows permuted (h, which, cph)
__device__ fp16 g_w_proj[CC * CC];
__device__ float g_c[NB * CC];
__device__ float g_x[NB * SS * CC];
__device__ fp16 g_q16[64 * SS * 64];
__device__ fp16 g_k16[64 * SS * 64];
__device__ fp16 g_v16[64 * SS * 64];

__device__ __forceinline__ float mp_silu(float v) {
    return v / (1.f + __expf(-v)) * SILU_SCALE;
}
__device__ __forceinline__ uint32_t packf(float a, float b) {
    __half2 h = __floats2half2_rn(a, b);
    return *(uint32_t*)&h;
}
__device__ __forceinline__ uint32_t smem_u32(const void* p) {
    uint32_t a;
    asm("{ .reg .u64 t; cvta.to.shared.u64 t, %1; cvt.u32.u64 %0, t; }" : "=r"(a) : "l"(p));
    return a;
}
__device__ __forceinline__ void cpa16(uint32_t d, const void* s, int sz) {
    asm volatile("cp.async.cg.shared.global [%0], [%1], 16, %2;"
                 :: "r"(d), "l"(s), "r"(sz));
}
__device__ __forceinline__ void ldsm4(uint32_t* r, uint32_t addr) {
    asm volatile("ldmatrix.sync.aligned.m8n8.x4.shared.b16 {%0,%1,%2,%3}, [%4];"
                 : "=r"(r[0]), "=r"(r[1]), "=r"(r[2]), "=r"(r[3]) : "r"(addr));
}
__device__ __forceinline__ void ldsm4t(uint32_t* r, uint32_t addr) {
    asm volatile("ldmatrix.sync.aligned.m8n8.x4.trans.shared.b16 {%0,%1,%2,%3}, [%4];"
                 : "=r"(r[0]), "=r"(r[1]), "=r"(r[2]), "=r"(r[3]) : "r"(addr));
}
__device__ __forceinline__ void mma16816(float* c, const uint32_t* a, const uint32_t* b) {
    asm volatile(
        "mma.sync.aligned.m16n8k16.row.col.f32.f16.f16.f32 "
        "{%0,%1,%2,%3}, {%4,%5,%6,%7}, {%8,%9}, {%0,%1,%2,%3};"
        : "+f"(c[0]), "+f"(c[1]), "+f"(c[2]), "+f"(c[3])
        : "r"(a[0]), "r"(a[1]), "r"(a[2]), "r"(a[3]), "r"(b[0]), "r"(b[1]));
}
__device__ __forceinline__ uint32_t swz(uint32_t byteoff, uint32_t row) {
    return byteoff ^ ((row & 7u) * 16u);
}
__device__ __forceinline__ uint32_t ex2h2(uint32_t t) {
    uint32_t r;
    asm volatile("ex2.approx.f16x2 %0, %1;" : "=r"(r) : "r"(t));
    return r;
}

// ---------------- unified prep: weights + emb modulation + input split -----
__global__ void k_prep_all(const float* __restrict__ w_skip,
                           const float* __restrict__ w_res0,
                           const float* __restrict__ w_res1,
                           const float* __restrict__ w_qkv,
                           const float* __restrict__ w_proj,
                           const float* __restrict__ w_emb,
                           const float* __restrict__ emb_g,
                           const float* __restrict__ emb,
                           const float* __restrict__ xin) {
    int b = blockIdx.x;
    if (b >= 2048) {
        __shared__ float t[32][33];
        int blk = b - 2048;
        int sblk = blk & 31, rest = blk >> 5;
        int cblk = rest % 6, n = rest / 6;
        int s0 = sblk * 32, c0 = cblk * 32;
        int li = threadIdx.x & 31, gi = threadIdx.x >> 5;
#pragma unroll
        for (int it = 0; it < 4; it++) {
            int c = gi + it * 8;
            t[c][li] = xin[((long)n * CIN + c0 + c) * SS + s0 + li];
        }
        __syncthreads();
#pragma unroll
        for (int it = 0; it < 4; it++) {
            int s = gi + it * 8;
            g_a16[((long)n * SS + s0 + s) * CIN + c0 + li] = __float2half(t[li][s]);
        }
        return;
    }
    const float* src;
    fp16* dst = nullptr;
    int cin, taps = 1, o, perm = 0;
    float gain = 1.f;
    bool isf32 = false;
    if (b < 256)       { src = w_skip; dst = g_w_skip; cin = CIN; o = b; }
    else if (b < 512)  { src = w_res0; dst = g_w_res0; cin = CC; taps = 9; o = b - 256; }
    else if (b < 768)  { src = w_res1; dst = g_w_res1; cin = CC; taps = 9; o = b - 512; }
    else if (b < 1536) { src = w_qkv;  dst = g_w_qkv;  cin = CC; o = b - 768; perm = 1; }
    else if (b < 1792) { src = w_proj; dst = g_w_proj; cin = CC; o = b - 1536; }
    else               { src = w_emb;  cin = CE; o = b - 1792; gain = *emb_g; isf32 = true; }

    int fan = cin * taps;
    const float* row = src + (long)o * fan;
    float s = 0.f;
    for (int i = threadIdx.x; i < fan; i += 256) { float v = row[i]; s += v * v; }
    __shared__ float red[256];
    red[threadIdx.x] = s;
    __syncthreads();
    for (int off = 128; off > 0; off >>= 1) {
        if (threadIdx.x < off) red[threadIdx.x] += red[threadIdx.x + off];
        __syncthreads();
    }
    float sf = sqrtf((float)fan);
    float scale = gain / (sf * (EPSV + sqrtf(red[0]) / sf));
    if (isf32) {
        __shared__ float srow[CE];
        for (int i = threadIdx.x; i < CE; i += 256) srow[i] = row[i] * scale;
        __syncthreads();
        int wid = threadIdx.x >> 5, lane = threadIdx.x & 31;
#pragma unroll
        for (int rep = 0; rep < 2; rep++) {
            int n = wid * 2 + rep;
            const float* e = emb + n * CE;
            float sum = 0.f;
            for (int k = lane; k < CE; k += 32) sum += e[k] * srow[k];
#pragma unroll
            for (int o2 = 16; o2 > 0; o2 >>= 1)
                sum += __shfl_xor_sync(0xffffffffu, sum, o2);
            if (lane == 0) g_c[n * CC + o] = sum + 1.0f;
        }
        return;
    }
    int od = o;
    if (perm) {
        int h = o / 192, r = o - h * 192;
        od = h * 192 + (r % 3) * 64 + r / 3;
    }
    fp16* drow = dst + (long)od * fan;
    if (taps == 1) {
        for (int i = threadIdx.x; i < fan; i += 256)
            drow[i] = __float2half(row[i] * scale);
    } else {
        for (int i = threadIdx.x; i < fan; i += 256) {
            int tap = i >> 8, ci = i & 255;
            drow[i] = __float2half(row[ci * 9 + tap] * scale);
        }
    }
}

// ---------------- fused skip conv (192->256) + pixel norm + silu -----------
#define SSTAGE 49152
#define SSMEM  (3 * SSTAGE)
__global__ __launch_bounds__(512, 1) void k_skipnorm(const fp16* __restrict__ inA,
                                                     const fp16* __restrict__ wA) {
    extern __shared__ char smem[];
    const int tid = threadIdx.x, lane = tid & 31, wid = tid >> 5;
    const int n = blockIdx.y, pxb = blockIdx.x * 128;
    const int wco = wid >> 2, wpx = wid & 3;
    const uint32_t sbase = smem_u32(smem);

    float acc[64];
#pragma unroll
    for (int i = 0; i < 64; i++) acc[i] = 0.f;

    auto load_chunk = [&](int c, int stage) {
        int ci0 = c << 6;
        uint32_t b = sbase + stage * SSTAGE;
#pragma unroll
        for (int rep = 0; rep < 4; rep++) {
            int idx = tid + rep * 512;
            int r = idx >> 3, seg = idx & 7;
            long aoff = (long)r * CIN + ci0 + seg * 8;
            cpa16(b + r * 128 + swz(seg * 16, r), wA + aoff, 16);
        }
#pragma unroll
        for (int rep = 0; rep < 2; rep++) {
            int idx = tid + rep * 512;
            int p = idx >> 3, seg = idx & 7;
            long soff = ((long)n * SS + pxb + p) * CIN + ci0 + seg * 8;
            cpa16(b + 32768 + p * 128 + swz(seg * 16, p), inA + soff, 16);
        }
        asm volatile("cp.async.commit_group;" ::: "memory");
    };

    load_chunk(0, 0);
    load_chunk(1, 1);
    load_chunk(2, 2);
    for (int c = 0; c < 3; c++) {
        if (c + 1 < 3) {
            asm volatile("cp.async.wait_group 1;" ::: "memory");
        } else {
            asm volatile("cp.async.wait_group 0;" ::: "memory");
        }
        __syncthreads();
        uint32_t b = sbase + c * SSTAGE;
#pragma unroll
        for (int k16 = 0; k16 < 4; k16++) {
            uint32_t Bh[8];
#pragma unroll
            for (int t = 0; t < 2; t++) {
                int sub = lane >> 3, r7 = lane & 7;
                uint32_t prow = wpx * 32 + (2 * t + (sub >> 1)) * 8 + r7;
                ldsm4(&Bh[4 * t],
                      b + 32768 + prow * 128 + swz(k16 * 32 + (sub & 1) * 16, prow));
            }
#pragma unroll
            for (int mt = 0; mt < 4; mt++) {
                uint32_t Ah[4];
                uint32_t mrow = wco * 64 + mt * 16 + (lane & 15);
                ldsm4(Ah, b + mrow * 128 + swz(k16 * 32 + (lane >> 4) * 16, mrow));
#pragma unroll
                for (int nt = 0; nt < 4; nt++)
                    mma16816(acc + mt * 16 + nt * 4, Ah, &Bh[2 * nt]);
            }
        }
        __syncthreads();
    }

    float* sT = (float*)smem;
#pragma unroll
    for (int mt = 0; mt < 4; mt++)
#pragma unroll
        for (int nt = 0; nt < 4; nt++)
#pragma unroll
            for (int r = 0; r < 4; r++) {
                int row = wco * 64 + mt * 16 + (lane >> 2) + ((r >> 1) << 3);
                int col = wpx * 32 + nt * 8 + ((lane & 3) << 1) + (r & 1);
                sT[col * 260 + row] = acc[mt * 16 + nt * 4 + r];
            }
    __syncthreads();

    int px = tid >> 2, q = tid & 3;
    float* sRow = sT + px * 260 + q * 64;
    float sum = 0.f;
#pragma unroll
    for (int j = 0; j < 64; j++) sum += sRow[j] * sRow[j];
    sum += __shfl_xor_sync(0xffffffffu, sum, 1);
    sum += __shfl_xor_sync(0xffffffffu, sum, 2);
    float scale = 1.f / (EPSV + sqrtf(sum) * 0.0625f);
    long ob = ((long)n * SS + pxb + px) * CC + q * 64;
#pragma unroll
    for (int j = 0; j < 64; j += 4) {
        float4 v = *(const float4*)&sRow[j];
        v.x *= scale; v.y *= scale; v.z *= scale; v.w *= scale;
        *(float4*)&g_x[ob + j] = v;
        *(uint2*)(g_a16 + ob + j) =
            make_uint2(packf(mp_silu(v.x), mp_silu(v.y)),
                       packf(mp_silu(v.z), mp_silu(v.w)));
    }
}

// ---------------- 3x3 conv via halo tile: input loaded ONCE per ci-chunk ----
// B-tiles for all 9 taps synthesized by ldsm row-address shifts.
// smem: B halo 2 x 26624 (208 rows x 128B), A 3 stages x 16384.
#define CB_OFF0 0
#define CB_OFF1 26624
#define CA_OFF  53248
#define CSMEM   (53248 + 3 * 16384)
__global__ __launch_bounds__(256, 2) void k_conv3(
    const fp16* __restrict__ inA, const fp16* __restrict__ wA,
    float* __restrict__ outF, fp16* __restrict__ out16,
    const float* __restrict__ res, const float* __restrict__ cvec,
    int mode) {
    extern __shared__ char smem[];
    const int tid = threadIdx.x, lane = tid & 31, wid = tid >> 5;
    const int n = blockIdx.z, co0 = blockIdx.y * 128, pxb = blockIdx.x * 128;
    const int h0 = blockIdx.x * 4;
    const int wco = wid >> 2, wpx = wid & 3;
    const uint32_t sbase = smem_u32(smem);
    const uint32_t bB[2] = {sbase + CB_OFF0, sbase + CB_OFF1};

    float acc[64];
#pragma unroll
    for (int i = 0; i < 64; i++) acc[i] = 0.f;

    // halo: 6 rows (h0-1..h0+4) x 34 cols (-1..32) = 204 pixel-rows of 128B
    auto loadB = [&](int cic, int buf) {
        uint32_t b = bB[buf];
        for (int idx = tid; idx < 1632; idx += 256) {
            int r = idx >> 3, seg = idx & 7;
            int ry = r / 34;
            int rx = r - ry * 34;
            int hy = h0 + ry - 1, wx = rx - 1;
            int valid = ((unsigned)hy < 32u) && ((unsigned)wx < 32u);
            long soff = ((long)n * SS + (valid ? hy * 32 + wx : 0)) * CC
                        + cic * 64 + seg * 8;
            cpa16(b + r * 128 + swz(seg * 16, r), inA + soff, valid ? 16 : 0);
        }
    };
    auto loadA = [&](int g, int stg) {    // g = cic*9 + tap
        int cic = g / 9, tap = g - cic * 9;
        uint32_t b = sbase + CA_OFF + stg * 16384;
#pragma unroll
        for (int rep = 0; rep < 4; rep++) {
            int idx = tid + rep * 256;
            int r = idx >> 3, seg = idx & 7;
            long aoff = (long)(co0 + r) * 2304 + tap * 256 + cic * 64 + seg * 8;
            cpa16(b + r * 128 + swz(seg * 16, r), wA + aoff, 16);
        }
    };

    // per-lane B fragment row constants (two 16-px groups)
    const int sub = lane >> 3, r7 = lane & 7;
    int srow_base[2];
#pragma unroll
    for (int t = 0; t < 2; t++) {
        int p = wpx * 32 + (2 * t + (sub >> 1)) * 8 + r7;
        int py = p >> 5, pw = p & 31;
        srow_base[t] = (py + 1) * 34 + pw + 1;   // tap (0,0) position
    }
    const uint32_t bk_half = (sub & 1) * 16;

    // prologue
    loadB(0, 0);
    loadA(0, 0);
    asm volatile("cp.async.commit_group;" ::: "memory");
    loadA(1, 1);
    asm volatile("cp.async.commit_group;" ::: "memory");

    for (int cic = 0; cic < 4; cic++) {
        uint32_t bbuf = bB[cic & 1];
        for (int tap = 0; tap < 9; tap++) {
            int g = cic * 9 + tap;
            if (g + 1 < 36) {
                asm volatile("cp.async.wait_group 1;" ::: "memory");
            } else {
                asm volatile("cp.async.wait_group 0;" ::: "memory");
            }
            __syncthreads();
            if (g + 2 < 36) loadA(g + 2, (g + 2) % 3);
            if (tap == 4 && cic < 3) loadB(cic + 1, (cic + 1) & 1);
            asm volatile("cp.async.commit_group;" ::: "memory");

            int dy = tap / 3 - 1, dx = tap - (tap / 3) * 3 - 1;
            int pd = dy * 34 + dx;
            uint32_t broff[2], bxor[2];
#pragma unroll
            for (int t = 0; t < 2; t++) {
                int srow = srow_base[t] + pd;
                broff[t] = bbuf + (uint32_t)srow * 128;
                bxor[t] = ((uint32_t)srow & 7u) * 16u;
            }
            uint32_t ab = sbase + CA_OFF + (g % 3) * 16384;
#pragma unroll
            for (int k16 = 0; k16 < 4; k16++) {
                uint32_t Bh[8];
#pragma unroll
                for (int t = 0; t < 2; t++)
                    ldsm4(&Bh[4 * t],
                          broff[t] + (((uint32_t)(k16 * 32) + bk_half) ^ bxor[t]));
#pragma unroll
                for (int mt = 0; mt < 4; mt++) {
                    uint32_t Ah[4];
                    uint32_t mrow = wco * 64 + mt * 16 + (lane & 15);
                    ldsm4(Ah, ab + mrow * 128 + swz(k16 * 32 + (lane >> 4) * 16, mrow));
#pragma unroll
                    for (int nt = 0; nt < 4; nt++)
                        mma16816(acc + mt * 16 + nt * 4, Ah, &Bh[2 * nt]);
                }
            }
        }
    }
    __syncthreads();

    // ---- single-round epilogue ----
    float* sT = (float*)smem;
#pragma unroll
    for (int mt = 0; mt < 4; mt++)
#pragma unroll
        for (int nt = 0; nt < 4; nt++)
#pragma unroll
            for (int r = 0; r < 4; r++) {
                int row = wco * 64 + mt * 16 + (lane >> 2) + ((r >> 1) << 3);
                int col = wpx * 32 + nt * 8 + ((lane & 3) << 1) + (r & 1);
                sT[col * 132 + row] = acc[mt * 16 + nt * 4 + r];
            }
    __syncthreads();

    int px = tid >> 1, half = tid & 1;
    long srow2 = (long)n * SS + pxb + px;
    float* sRow = sT + px * 132 + half * 64;
    int cg0 = co0 + half * 64;
    if (mode == 1) {
        long ob = srow2 * CC + cg0;
#pragma unroll
        for (int j = 0; j < 64; j += 4) {
            float4 v = *(const float4*)&sRow[j];
            float4 cv = *(const float4*)&cvec[n * CC + cg0 + j];
            *(uint2*)(out16 + ob + j) =
                make_uint2(packf(mp_silu(v.x * cv.x), mp_silu(v.y * cv.y)),
                           packf(mp_silu(v.z * cv.z), mp_silu(v.w * cv.w)));
        }
    } else {
        long ob = srow2 * CC + cg0;
#pragma unroll
        for (int j = 0; j < 64; j += 4) {
            float4 v = *(const float4*)&sRow[j];
            float4 r4 = *(const float4*)&res[ob + j];
            v.x = CA * r4.x + CB * v.x; v.y = CA * r4.y + CB * v.y;
            v.z = CA * r4.z + CB * v.z; v.w = CA * r4.w + CB * v.w;
            *(float4*)&outF[ob + j] = v;
            *(uint2*)(out16 + ob + j) = make_uint2(packf(v.x, v.y), packf(v.z, v.w));
        }
    }
}

// ---------------- fp16 mma.sync GEMM (1x1 convs): 128x128, K=64 ------------
#define GSTAGE 32768
#define GSMEM  (3 * GSTAGE)
__global__ __launch_bounds__(256, 2) void k_gemm(
    const fp16* __restrict__ inA, const fp16* __restrict__ wA,
    float* __restrict__ outF, fp16* __restrict__ out16,
    const float* __restrict__ res, const float* __restrict__ cvec,
    int cin, int cout, int mode) {
    extern __shared__ char smem[];
    const int tid = threadIdx.x, lane = tid & 31, wid = tid >> 5;
    const int n = blockIdx.z, co0 = blockIdx.y * 128, pxb = blockIdx.x * 128;
    const int wco = wid >> 2, wpx = wid & 3;
    const int nch = cin >> 6;
    const uint32_t sbase = smem_u32(smem);

    float acc[64];
#pragma unroll
    for (int i = 0; i < 64; i++) acc[i] = 0.f;

    auto load_chunk = [&](int c, int stage) {
        int ci0 = c << 6;
        uint32_t b = sbase + stage * GSTAGE;
#pragma unroll
        for (int rep = 0; rep < 4; rep++) {
            int idx = tid + rep * 256;
            int r = idx >> 3, seg = idx & 7;
            long aoff = (long)(co0 + r) * cin + ci0 + seg * 8;
            cpa16(b + r * 128 + swz(seg * 16, r), wA + aoff, 16);
        }
#pragma unroll
        for (int rep = 0; rep < 4; rep++) {
            int idx = tid + rep * 256;
            int p = idx >> 3, seg = idx & 7;
            long soff = ((long)n * SS + pxb + p) * cin + ci0 + seg * 8;
            cpa16(b + 16384 + p * 128 + swz(seg * 16, p), inA + soff, 16);
        }
        asm volatile("cp.async.commit_group;" ::: "memory");
    };

    load_chunk(0, 0);
    if (nch > 1) load_chunk(1, 1);
    int stage = 0;
    for (int c = 0; c < nch; c++) {
        if (c + 1 < nch) {
            asm volatile("cp.async.wait_group 1;" ::: "memory");
        } else {
            asm volatile("cp.async.wait_group 0;" ::: "memory");
        }
        __syncthreads();
        if (c + 2 < nch) {
            int ps = stage + 2;
            if (ps >= 3) ps -= 3;
            load_chunk(c + 2, ps);
        }
        uint32_t b = sbase + stage * GSTAGE;
#pragma unroll
        for (int k16 = 0; k16 < 4; k16++) {
            uint32_t Bh[8];
#pragma unroll
            for (int t = 0; t < 2; t++) {
                int sub = lane >> 3, r7 = lane & 7;
                uint32_t prow = wpx * 32 + (2 * t + (sub >> 1)) * 8 + r7;
                ldsm4(&Bh[4 * t],
                      b + 16384 + prow * 128 + swz(k16 * 32 + (sub & 1) * 16, prow));
            }
#pragma unroll
            for (int mt = 0; mt < 4; mt++) {
                uint32_t Ah[4];
                uint32_t mrow = wco * 64 + mt * 16 + (lane & 15);
                ldsm4(Ah, b + mrow * 128 + swz(k16 * 32 + (lane >> 4) * 16, mrow));
#pragma unroll
                for (int nt = 0; nt < 4; nt++)
                    mma16816(acc + mt * 16 + nt * 4, Ah, &Bh[2 * nt]);
            }
        }
        stage++;
        if (stage >= 3) stage = 0;
    }
    __syncthreads();

    float* sT = (float*)smem;
#pragma unroll
    for (int mt = 0; mt < 4; mt++)
#pragma unroll
        for (int nt = 0; nt < 4; nt++)
#pragma unroll
            for (int r = 0; r < 4; r++) {
                int row = wco * 64 + mt * 16 + (lane >> 2) + ((r >> 1) << 3);
                int col = wpx * 32 + nt * 8 + ((lane & 3) << 1) + (r & 1);
                sT[col * 132 + row] = acc[mt * 16 + nt * 4 + r];
            }
    __syncthreads();

    int px = tid >> 1, half = tid & 1;
    long srow = (long)n * SS + pxb + px;
    float* sRow = sT + px * 132 + half * 64;
    int cg0 = co0 + half * 64;
    if (mode == 3) {
        float sum = 0.f;
#pragma unroll
        for (int j = 0; j < 64; j++) sum += sRow[j] * sRow[j];
        float scale = 1.f / (EPSV + sqrtf(sum) * 0.125f);
        int g64 = (cg0 >> 6);
        int h = g64 / 3, which = g64 - h * 3;
        fp16* dst = (which == 0) ? g_q16 : (which == 1) ? g_k16 : g_v16;
        long ob = ((long)(n * NHEAD + h) * SS + pxb + px) * 64;
#pragma unroll
        for (int j = 0; j < 64; j += 2)
            *(uint32_t*)(dst + ob + j) = packf(sRow[j] * scale, sRow[j + 1] * scale);
    } else {
        long ob = srow * CC + cg0;
#pragma unroll
        for (int j = 0; j < 64; j += 4) {
            float4 v = *(const float4*)&sRow[j];
            float4 r4 = *(const float4*)&res[ob + j];
            v.x = fminf(fmaxf(CA * r4.x + CB * v.x, -256.f), 256.f);
            v.y = fminf(fmaxf(CA * r4.y + CB * v.y, -256.f), 256.f);
            v.z = fminf(fmaxf(CA * r4.z + CB * v.z, -256.f), 256.f);
            v.w = fminf(fmaxf(CA * r4.w + CB * v.w, -256.f), 256.f);
            *(float4*)&sRow[j] = v;
        }
        __syncthreads();
        int co = tid >> 1, hp = tid & 1;
        float* op = outF + ((long)n * CC + co0 + co) * SS + pxb + hp * 64;
#pragma unroll
        for (int j = 0; j < 64; j += 4) {
            float4 v;
            v.x = sT[(hp * 64 + j + 0) * 132 + co];
            v.y = sT[(hp * 64 + j + 1) * 132 + co];
            v.z = sT[(hp * 64 + j + 2) * 132 + co];
            v.w = sT[(hp * 64 + j + 3) * 132 + co];
            *(float4*)&op[j] = v;
        }
    }
}

// ---------------- fp16 MMA flash attention: 128-key tiles ----------------
#define ASTAGE 36864
#define ATT_SMEM (3 * ASTAGE)
__global__ __launch_bounds__(256, 2) void k_fattn() {
    extern __shared__ char smem[];
    const int tid = threadIdx.x, lane = tid & 31, wid = tid >> 5;
    const int nh = blockIdx.y, qb = blockIdx.x * 128;
    const int n = nh >> 2, h = nh & 3;
    const uint32_t sb = smem_u32(smem);
    const long nhb = (long)nh * SS * 64;
    const fp16* kp = g_k16 + nhb;
    const fp16* vp = g_v16 + nhb;
    const float C1 = 0.125f * 1.4426950408889634f;
    const float C2 = 8.0f * 1.4426950408889634f;

    {
        const fp16* qp = g_q16 + nhb + (long)qb * 64;
        for (int i = tid; i < 1024; i += 256) {
            int r = i >> 3, seg = i & 7;
            cpa16(sb + r * 144 + seg * 16, qp + r * 64 + seg * 8, 16);
        }
        asm volatile("cp.async.commit_group;" ::: "memory");
        asm volatile("cp.async.wait_group 0;" ::: "memory");
        __syncthreads();
    }
    uint32_t qf[4][4];
    {
        int r = wid * 16 + (lane & 15);
        int halfk = lane >> 4;
#pragma unroll
        for (int kc = 0; kc < 4; kc++)
            ldsm4(qf[kc], sb + r * 144 + (kc * 16 + halfk * 8) * 2);
    }
    __syncthreads();

    auto load_kv = [&](int t, int stg) {
        uint32_t b = sb + stg * ASTAGE;
#pragma unroll
        for (int rep = 0; rep < 4; rep++) {
            int i = tid + rep * 256;
            int r = i >> 3, seg = i & 7;
            long off = ((long)t * 128 + r) * 64 + seg * 8;
            uint32_t d = b + r * 144 + seg * 16;
            cpa16(d, kp + off, 16);
            cpa16(d + 18432, vp + off, 16);
        }
        asm volatile("cp.async.commit_group;" ::: "memory");
    };

    float l0 = 0.f, l1 = 0.f;
    float acc[8][4];
#pragma unroll
    for (int j = 0; j < 8; j++)
#pragma unroll
        for (int i = 0; i < 4; i++) acc[j][i] = 0.f;

    load_kv(0, 0);
    load_kv(1, 1);
    int stg = 0;
    for (int t = 0; t < 8; t++) {
        if (t + 1 < 8) {
            asm volatile("cp.async.wait_group 1;" ::: "memory");
        } else {
            asm volatile("cp.async.wait_group 0;" ::: "memory");
        }
        __syncthreads();
        if (t + 2 < 8) {
            int ps = stg + 2;
            if (ps >= 3) ps -= 3;
            load_kv(t + 2, ps);
        }
        uint32_t kb = sb + stg * ASTAGE;
        const int g = lane >> 3, r7 = lane & 7;

        uint32_t pc01[16], pc23[16];
#pragma unroll
        for (int ntp = 0; ntp < 8; ntp++) {
            float s0[4] = {0.f, 0.f, 0.f, 0.f};
            float s1[4] = {0.f, 0.f, 0.f, 0.f};
#pragma unroll
            for (int kc = 0; kc < 4; kc++) {
                uint32_t bh[4];
                ldsm4(bh, kb + (ntp * 16 + (g >> 1) * 8 + r7) * 144
                          + (kc * 16 + (g & 1) * 8) * 2);
                mma16816(s0, qf[kc], bh);
                mma16816(s1, qf[kc], bh + 2);
            }
            uint32_t a0 = ex2h2(packf(s0[0] * C1 - C2, s0[1] * C1 - C2));
            uint32_t b0 = ex2h2(packf(s0[2] * C1 - C2, s0[3] * C1 - C2));
            uint32_t a1 = ex2h2(packf(s1[0] * C1 - C2, s1[1] * C1 - C2));
            uint32_t b1 = ex2h2(packf(s1[2] * C1 - C2, s1[3] * C1 - C2));
            pc01[2 * ntp] = a0; pc23[2 * ntp] = b0;
            pc01[2 * ntp + 1] = a1; pc23[2 * ntp + 1] = b1;
            float2 fa0 = __half22float2(*(__half2*)&a0);
            float2 fb0 = __half22float2(*(__half2*)&b0);
            float2 fa1 = __half22float2(*(__half2*)&a1);
            float2 fb1 = __half22float2(*(__half2*)&b1);
            l0 += fa0.x + fa0.y + fa1.x + fa1.y;
            l1 += fb0.x + fb0.y + fb1.x + fb1.y;
        }
#pragma unroll
        for (int kk = 0; kk < 8; kk++) {
            uint32_t ph[4];
            ph[0] = pc01[2 * kk];
            ph[1] = pc23[2 * kk];
            ph[2] = pc01[2 * kk + 1];
            ph[3] = pc23[2 * kk + 1];
#pragma unroll
            for (int ctp = 0; ctp < 4; ctp++) {
                uint32_t vh4[4];
                ldsm4t(vh4, kb + 18432 + (kk * 16 + (g & 1) * 8 + r7) * 144
                            + (ctp * 16 + (g >> 1) * 8) * 2);
                mma16816(acc[2 * ctp], ph, vh4);
                mma16816(acc[2 * ctp + 1], ph, vh4 + 2);
            }
        }
        stg++;
        if (stg >= 3) stg = 0;
    }

    l0 += __shfl_xor_sync(0xffffffffu, l0, 1);
    l0 += __shfl_xor_sync(0xffffffffu, l0, 2);
    l1 += __shfl_xor_sync(0xffffffffu, l1, 1);
    l1 += __shfl_xor_sync(0xffffffffu, l1, 2);
    float i0 = 1.f / l0, i1 = 1.f / l1;
    int t4 = lane & 3;
    int s0r = qb + wid * 16 + (lane >> 2);
    long b0 = ((long)n * SS + s0r) * CC + h * 64;
    long b1 = ((long)n * SS + s0r + 8) * CC + h * 64;
#pragma unroll
    for (int j = 0; j < 8; j++) {
        int ch = j * 8 + t4 * 2;
        *(uint32_t*)(g_b16 + b0 + ch) = packf(acc[j][0] * i0, acc[j][1] * i0);
        *(uint32_t*)(g_b16 + b1 + ch) = packf(acc[j][2] * i1, acc[j][3] * i1);
    }
}

// ---------------- launcher ----------------
extern "C" void kernel_launch(void* const* d_in, const int* in_sizes, int n_in,
                              void* d_out, int out_size) {
    const float* x      = (const float*)d_in[0];
    const float* emb    = (const float*)d_in[1];
    const float* w_skip = (const float*)d_in[2];
    const float* w_res0 = (const float*)d_in[3];
    const float* w_res1 = (const float*)d_in[4];
    const float* w_emb  = (const float*)d_in[5];
    const float* emb_g  = (const float*)d_in[6];
    const float* w_qkv  = (const float*)d_in[7];
    const float* w_proj = (const float*)d_in[8];
    float* out = (float*)d_out;

    fp16 *p_a16, *p_b16, *pw_skip, *pw_res0, *pw_res1, *pw_qkv, *pw_proj;
    float *p_x, *p_c;
    cudaGetSymbolAddress((void**)&p_a16, g_a16);
    cudaGetSymbolAddress((void**)&p_b16, g_b16);
    cudaGetSymbolAddress((void**)&pw_skip, g_w_skip);
    cudaGetSymbolAddress((void**)&pw_res0, g_w_res0);
    cudaGetSymbolAddress((void**)&pw_res1, g_w_res1);
    cudaGetSymbolAddress((void**)&pw_qkv, g_w_qkv);
    cudaGetSymbolAddress((void**)&pw_proj, g_w_proj);
    cudaGetSymbolAddress((void**)&p_x, g_x);
    cudaGetSymbolAddress((void**)&p_c, g_c);

    cudaFuncSetAttribute(k_gemm, cudaFuncAttributeMaxDynamicSharedMemorySize, GSMEM);
    cudaFuncSetAttribute(k_conv3, cudaFuncAttributeMaxDynamicSharedMemorySize, CSMEM);
    cudaFuncSetAttribute(k_fattn, cudaFuncAttributeMaxDynamicSharedMemorySize, ATT_SMEM);
    cudaFuncSetAttribute(k_skipnorm, cudaFuncAttributeMaxDynamicSharedMemorySize, SSMEM);

    k_prep_all<<<2048 + 3072, 256>>>(w_skip, w_res0, w_res1, w_qkv, w_proj,
                                     w_emb, emb_g, emb, x);
    k_skipnorm<<<dim3(8, NB), 512, SSMEM>>>(p_a16, pw_skip);
    // res0: silu(conv3x3 * c) -> b16 (halo-tile conv)
    k_conv3<<<dim3(8, 2, NB), 256, CSMEM>>>(p_a16, pw_res0, nullptr, p_b16,
                                            nullptr, p_c, 1);
    // res1: x = CA*x + CB*conv3x3 -> fp32 x + a16
    k_conv3<<<dim3(8, 2, NB), 256, CSMEM>>>(p_b16, pw_res1, p_x, p_a16,
                                            p_x, nullptr, 2);
    // qkv conv (256->768) + fused head-channel norm -> q/k/v fp16
    k_gemm<<<dim3(8, 6, NB), 256, GSMEM>>>(p_a16, pw_qkv, nullptr, nullptr,
                                           nullptr, nullptr, CC, 3 * CC, 3);
    // fp16 MMA flash attention (128-key tiles) -> b16
    k_fattn<<<dim3(SS / 128, NB * NHEAD), 256, ATT_SMEM>>>();
    // proj + mp_sum + clip -> d_out (NCHW)
    k_gemm<<<dim3(8, 2, NB), 256, GSMEM>>>(p_b16, pw_proj, out, nullptr,
                                           p_x, nullptr, CC, CC, 4);
}